// round 3
// baseline (speedup 1.0000x reference)
#include <cuda_runtime.h>
#include <cuda_bf16.h>

// Skipgram negative-sampling loss — single fused kernel.
// Inputs (metadata order):
//   d_in[0] input_idx  int32  [N]
//   d_in[1] output_idx int32  [N]
//   d_in[2] neg_idx    int32  [N, K]
//   d_in[3] W_in       fp32   [N_WORDS, D]
//   d_in[4] W_out      fp32   [N_WORDS, D]
// Output: scalar fp32 loss.

#define N_SAMPLES 65536
#define DIMS      128
#define KNEG      10
#define WARPS_PER_BLOCK 8
#define NBLOCKS   (N_SAMPLES / WARPS_PER_BLOCK)   // 8192
#define NTHREADS  (WARPS_PER_BLOCK * 32)          // 256

// Static device scratch (no allocation). g_ticket wraps back to 0 every
// launch via atomicInc(..., NBLOCKS-1) -> deterministic across graph replays.
__device__ float        g_partials[NBLOCKS];
__device__ unsigned int g_ticket;   // zero-initialized

__device__ __forceinline__ float warp_sum(float v) {
#pragma unroll
    for (int o = 16; o > 0; o >>= 1)
        v += __shfl_xor_sync(0xffffffff, v, o);
    return v;
}

__device__ __forceinline__ double warp_sum_d(double v) {
#pragma unroll
    for (int o = 16; o > 0; o >>= 1)
        v += __shfl_xor_sync(0xffffffff, v, o);
    return v;
}

// numerically stable log(sigmoid(x)) = min(x,0) - log1p(exp(-|x|))
__device__ __forceinline__ float logsig(float x) {
    return fminf(x, 0.0f) - log1pf(__expf(-fabsf(x)));
}

__global__ __launch_bounds__(NTHREADS)
void sg_fused_kernel(const int* __restrict__ input_idx,
                     const int* __restrict__ output_idx,
                     const int* __restrict__ neg_idx,
                     const float* __restrict__ W_in,
                     const float* __restrict__ W_out,
                     float* __restrict__ out) {
    const int warp = threadIdx.x >> 5;
    const int lane = threadIdx.x & 31;
    const int n = blockIdx.x * WARPS_PER_BLOCK + warp;

    // --- fetch indices: coalesced neg_idx load by lanes 0..9, broadcast ---
    int my_neg = 0;
    if (lane < KNEG) my_neg = neg_idx[n * KNEG + lane];
    const int ii = input_idx[n];    // uniform -> single broadcast request
    const int oi = output_idx[n];

    // --- gather 12 rows; each lane holds one float4 of a 128-float row ---
    const float4* a4 = reinterpret_cast<const float4*>(W_in + (size_t)ii * DIMS);
    float4 a = __ldg(a4 + lane);

    float4 b[KNEG + 1];
    {
        const float4* p = reinterpret_cast<const float4*>(W_out + (size_t)oi * DIMS);
        b[0] = __ldg(p + lane);
    }
#pragma unroll
    for (int k = 0; k < KNEG; k++) {
        int idx = __shfl_sync(0xffffffff, my_neg, k);
        const float4* p = reinterpret_cast<const float4*>(W_out + (size_t)idx * DIMS);
        b[k + 1] = __ldg(p + lane);
    }

    // --- per-lane partial dots ---
    float part[KNEG + 1];
#pragma unroll
    for (int j = 0; j < KNEG + 1; j++)
        part[j] = a.x * b[j].x + a.y * b[j].y + a.z * b[j].z + a.w * b[j].w;

    // --- warp reductions + log-sigmoid ---
    float local = 0.0f;
#pragma unroll
    for (int j = 0; j < KNEG + 1; j++) {
        float d = warp_sum(part[j]);
        if (lane == 0)
            local += logsig(j == 0 ? d : -d);
    }

    // --- block reduce -> per-block partial ---
    __shared__ float s[WARPS_PER_BLOCK];
    if (lane == 0) s[warp] = local;
    __syncthreads();
    __shared__ bool is_last;
    if (threadIdx.x == 0) {
        float t = 0.0f;
#pragma unroll
        for (int i = 0; i < WARPS_PER_BLOCK; i++) t += s[i];
        g_partials[blockIdx.x] = t;
        __threadfence();
        unsigned int ticket = atomicInc(&g_ticket, NBLOCKS - 1);
        is_last = (ticket == NBLOCKS - 1);
    }
    __syncthreads();

    // --- last block finishes: reduce 8192 partials in double ---
    if (is_last) {
        double acc = 0.0;
        for (int i = threadIdx.x; i < NBLOCKS; i += NTHREADS)
            acc += (double)g_partials[i];
        acc = warp_sum_d(acc);
        __shared__ double sd[WARPS_PER_BLOCK];
        if (lane == 0) sd[warp] = acc;
        __syncthreads();
        if (threadIdx.x == 0) {
            double t = 0.0;
#pragma unroll
            for (int i = 0; i < WARPS_PER_BLOCK; i++) t += sd[i];
            out[0] = (float)(t / (double)N_SAMPLES);
        }
    }
}

extern "C" void kernel_launch(void* const* d_in, const int* in_sizes, int n_in,
                              void* d_out, int out_size) {
    const int*   input_idx  = (const int*)d_in[0];
    const int*   output_idx = (const int*)d_in[1];
    const int*   neg_idx    = (const int*)d_in[2];
    const float* W_in       = (const float*)d_in[3];
    const float* W_out      = (const float*)d_in[4];
    float* out = (float*)d_out;

    sg_fused_kernel<<<NBLOCKS, NTHREADS>>>(
        input_idx, output_idx, neg_idx, W_in, W_out, out);
}

// round 5
// speedup vs baseline: 1.6581x; 1.6581x over previous
#include <cuda_runtime.h>
#include <cuda_bf16.h>

// Skipgram negative-sampling loss — 2 launches, latency-optimized.
// Inputs (metadata order):
//   d_in[0] input_idx  int32  [N]
//   d_in[1] output_idx int32  [N]
//   d_in[2] neg_idx    int32  [N, K]
//   d_in[3] W_in       fp32   [N_WORDS, D]
//   d_in[4] W_out      fp32   [N_WORDS, D]
// Output: scalar fp32 loss.

#define N_SAMPLES 65536
#define DIMS      128
#define KNEG      10
#define NROWS     (KNEG + 1)      // 11 W_out rows per sample
#define WARPS_PER_BLOCK 8
#define NBLOCKS   (N_SAMPLES / WARPS_PER_BLOCK)   // 8192
#define NTHREADS  (WARPS_PER_BLOCK * 32)          // 256

__device__ float g_partials[NBLOCKS];

__device__ __forceinline__ float warp_sum(float v) {
#pragma unroll
    for (int o = 16; o > 0; o >>= 1)
        v += __shfl_xor_sync(0xffffffff, v, o);
    return v;
}

__device__ __forceinline__ double warp_sum_d(double v) {
#pragma unroll
    for (int o = 16; o > 0; o >>= 1)
        v += __shfl_xor_sync(0xffffffff, v, o);
    return v;
}

// fast log(sigmoid(x)) = -log(1 + exp(-x)); safe for |x| << 80, rel err ~2^-21
__device__ __forceinline__ float logsig_fast(float x) {
    return -__logf(1.0f + __expf(-x));
}

__device__ __forceinline__ float dot4(float4 a, float4 b) {
    return a.x * b.x + a.y * b.y + a.z * b.z + a.w * b.w;
}

__global__ __launch_bounds__(NTHREADS, 5)
void sg_compute_kernel(const int* __restrict__ input_idx,
                       const int* __restrict__ output_idx,
                       const int* __restrict__ neg_idx,
                       const float* __restrict__ W_in,
                       const float* __restrict__ W_out) {
    const int warp = threadIdx.x >> 5;
    const int lane = threadIdx.x & 31;
    const int n = blockIdx.x * WARPS_PER_BLOCK + warp;

    // --- independent scalar index loads (uniform across warp, issue early) ---
    int idx[NROWS];
    idx[0] = output_idx[n];
#pragma unroll
    for (int k = 0; k < KNEG; k++)
        idx[k + 1] = neg_idx[n * KNEG + k];
    const int ii = input_idx[n];

    // --- input row: each lane holds one float4 of the 128-float row ---
    float4 a = __ldg(reinterpret_cast<const float4*>(W_in + (size_t)ii * DIMS) + lane);

    // --- 3-deep rotated streaming of the 11 W_out rows ---
    float4 b0 = __ldg(reinterpret_cast<const float4*>(W_out + (size_t)idx[0] * DIMS) + lane);
    float4 b1 = __ldg(reinterpret_cast<const float4*>(W_out + (size_t)idx[1] * DIMS) + lane);
    float4 b2 = __ldg(reinterpret_cast<const float4*>(W_out + (size_t)idx[2] * DIMS) + lane);

    float local = 0.0f;
#pragma unroll
    for (int j = 0; j < NROWS; j++) {
        float p = dot4(a, b0);
        // rotate pipeline; issue next load before the reduction chain
        b0 = b1;
        b1 = b2;
        if (j + 3 < NROWS)
            b2 = __ldg(reinterpret_cast<const float4*>(W_out + (size_t)idx[j + 3] * DIMS) + lane);
        float d = warp_sum(p);
        // all lanes compute redundantly (same warp-issue cost, no predication)
        local += logsig_fast(j == 0 ? d : -d);
    }

    // --- block reduce -> per-block partial (plain store, no atomics) ---
    __shared__ float s[WARPS_PER_BLOCK];
    if (lane == 0) s[warp] = local;
    __syncthreads();
    if (threadIdx.x == 0) {
        float t = 0.0f;
#pragma unroll
        for (int i = 0; i < WARPS_PER_BLOCK; i++) t += s[i];
        g_partials[blockIdx.x] = t;
    }
}

__global__ __launch_bounds__(256)
void sg_finalize_kernel(float* __restrict__ out) {
    const int lane = threadIdx.x & 31;
    const int warp = threadIdx.x >> 5;
    double acc = 0.0;
    for (int i = threadIdx.x; i < NBLOCKS; i += 256)
        acc += (double)g_partials[i];
    acc = warp_sum_d(acc);
    __shared__ double sd[8];
    if (lane == 0) sd[warp] = acc;
    __syncthreads();
    if (threadIdx.x == 0) {
        double t = 0.0;
#pragma unroll
        for (int i = 0; i < 8; i++) t += sd[i];
        out[0] = (float)(t / (double)N_SAMPLES);
    }
}

extern "C" void kernel_launch(void* const* d_in, const int* in_sizes, int n_in,
                              void* d_out, int out_size) {
    const int*   input_idx  = (const int*)d_in[0];
    const int*   output_idx = (const int*)d_in[1];
    const int*   neg_idx    = (const int*)d_in[2];
    const float* W_in       = (const float*)d_in[3];
    const float* W_out      = (const float*)d_in[4];
    float* out = (float*)d_out;

    sg_compute_kernel<<<NBLOCKS, NTHREADS>>>(
        input_idx, output_idx, neg_idx, W_in, W_out);
    sg_finalize_kernel<<<1, 256>>>(out);
}

// round 6
// speedup vs baseline: 1.8453x; 1.1129x over previous
#include <cuda_runtime.h>
#include <cuda_bf16.h>

// Skipgram negative-sampling loss — ONE launch.
// Grid-wide reduction via a single packed u64 atomic:
//   bits [0:48)  fixed-point sum of block partials (bias 8192, scale 2^20)
//   bits [48:64) block-completion counter
// Integer adds are associative -> bit-deterministic across graph replays.
// The last block's atomicAdd return value already contains the full sum, so
// no threadfence / no second kernel / no L1 flush is needed.
//
// Inputs (metadata order):
//   d_in[0] input_idx  int32  [N]
//   d_in[1] output_idx int32  [N]
//   d_in[2] neg_idx    int32  [N, K]
//   d_in[3] W_in       fp32   [N_WORDS, D]
//   d_in[4] W_out      fp32   [N_WORDS, D]
// Output: scalar fp32 loss.

#define N_SAMPLES 65536
#define DIMS      128
#define KNEG      10
#define NROWS     (KNEG + 1)      // 11 W_out rows per sample
#define WARPS_PER_BLOCK 8
#define NBLOCKS   (N_SAMPLES / WARPS_PER_BLOCK)   // 8192
#define NTHREADS  (WARPS_PER_BLOCK * 32)          // 256

#define FP_BIAS   8192.0          // block partial is in (-8192, 0]
#define FP_SCALE  1048576.0       // 2^20

__device__ unsigned long long g_acc_pack;   // zero-initialized

__device__ __forceinline__ float warp_sum(float v) {
#pragma unroll
    for (int o = 16; o > 0; o >>= 1)
        v += __shfl_xor_sync(0xffffffff, v, o);
    return v;
}

// fast log(sigmoid(x)) = -log(1 + exp(-x)); safe for |x| << 80, rel err ~2^-21
__device__ __forceinline__ float logsig_fast(float x) {
    return -__logf(1.0f + __expf(-x));
}

__device__ __forceinline__ float dot4(float4 a, float4 b) {
    return a.x * b.x + a.y * b.y + a.z * b.z + a.w * b.w;
}

__global__ __launch_bounds__(NTHREADS, 5)
void sg_compute_kernel(const int* __restrict__ input_idx,
                       const int* __restrict__ output_idx,
                       const int* __restrict__ neg_idx,
                       const float* __restrict__ W_in,
                       const float* __restrict__ W_out,
                       float* __restrict__ out) {
    const int warp = threadIdx.x >> 5;
    const int lane = threadIdx.x & 31;
    const int n = blockIdx.x * WARPS_PER_BLOCK + warp;

    // --- independent scalar index loads (uniform across warp, issue early) ---
    int idx[NROWS];
    idx[0] = output_idx[n];
#pragma unroll
    for (int k = 0; k < KNEG; k++)
        idx[k + 1] = neg_idx[n * KNEG + k];
    const int ii = input_idx[n];

    // --- input row: each lane holds one float4 of the 128-float row ---
    float4 a = __ldg(reinterpret_cast<const float4*>(W_in + (size_t)ii * DIMS) + lane);

    // --- 3-deep rotated streaming of the 11 W_out rows ---
    float4 b0 = __ldg(reinterpret_cast<const float4*>(W_out + (size_t)idx[0] * DIMS) + lane);
    float4 b1 = __ldg(reinterpret_cast<const float4*>(W_out + (size_t)idx[1] * DIMS) + lane);
    float4 b2 = __ldg(reinterpret_cast<const float4*>(W_out + (size_t)idx[2] * DIMS) + lane);

    float local = 0.0f;
#pragma unroll
    for (int j = 0; j < NROWS; j++) {
        float p = dot4(a, b0);
        // rotate pipeline; issue next load before the reduction chain
        b0 = b1;
        b1 = b2;
        if (j + 3 < NROWS)
            b2 = __ldg(reinterpret_cast<const float4*>(W_out + (size_t)idx[j + 3] * DIMS) + lane);
        float d = warp_sum(p);
        // all lanes compute redundantly (same warp-issue cost, no predication)
        local += logsig_fast(j == 0 ? d : -d);
    }

    // --- block reduce ---
    __shared__ float s[WARPS_PER_BLOCK];
    if (lane == 0) s[warp] = local;
    __syncthreads();
    if (threadIdx.x == 0) {
        float t = 0.0f;
#pragma unroll
        for (int i = 0; i < WARPS_PER_BLOCK; i++) t += s[i];

        // fixed-point pack: value in [0, 2^34), counter at bit 48
        long long fixed = __double2ll_rn(((double)t + FP_BIAS) * FP_SCALE);
        unsigned long long add = (1ULL << 48) + (unsigned long long)fixed;
        unsigned long long old = atomicAdd(&g_acc_pack, add);

        if ((old >> 48) == NBLOCKS - 1) {
            // This block is last: old + add is the complete packed total.
            unsigned long long total = old + add;
            double sum = (double)(long long)(total & ((1ULL << 48) - 1)) / FP_SCALE
                         - (double)NBLOCKS * FP_BIAS;
            out[0] = (float)(sum / (double)N_SAMPLES);
            g_acc_pack = 0ULL;   // reset for next graph replay (no racers remain)
        }
    }
}

extern "C" void kernel_launch(void* const* d_in, const int* in_sizes, int n_in,
                              void* d_out, int out_size) {
    const int*   input_idx  = (const int*)d_in[0];
    const int*   output_idx = (const int*)d_in[1];
    const int*   neg_idx    = (const int*)d_in[2];
    const float* W_in       = (const float*)d_in[3];
    const float* W_out      = (const float*)d_in[4];
    float* out = (float*)d_out;

    sg_compute_kernel<<<NBLOCKS, NTHREADS>>>(
        input_idx, output_idx, neg_idx, W_in, W_out, out);
}

// round 8
// speedup vs baseline: 1.9175x; 1.0391x over previous
#include <cuda_runtime.h>
#include <cuda_bf16.h>

// Skipgram negative-sampling loss — ONE launch.
// Grid-wide reduction via a single packed u64 atomic (bit-deterministic):
//   bits [0:48)  fixed-point sum of block partials (bias 8192, scale 2^20)
//   bits [48:64) block-completion counter
// The last block's atomicAdd return already holds the full sum -> no fence.
//
// Table-row gathers use createpolicy L2::evict_last + ld.global.nc.L2::cache_hint
// so the 102MB embedding tables stay L2-resident (R6 measured ~86MB/launch of
// DRAM miss traffic from streaming self-eviction).
//
// Inputs (metadata order):
//   d_in[0] input_idx  int32  [N]
//   d_in[1] output_idx int32  [N]
//   d_in[2] neg_idx    int32  [N, K]
//   d_in[3] W_in       fp32   [N_WORDS, D]
//   d_in[4] W_out      fp32   [N_WORDS, D]
// Output: scalar fp32 loss.

#define N_SAMPLES 65536
#define DIMS      128
#define KNEG      10
#define NROWS     (KNEG + 1)      // 11 W_out rows per sample
#define WARPS_PER_BLOCK 8
#define NBLOCKS   (N_SAMPLES / WARPS_PER_BLOCK)   // 8192
#define NTHREADS  (WARPS_PER_BLOCK * 32)          // 256

#define FP_BIAS   8192.0          // block partial is in (-8192, 0]
#define FP_SCALE  1048576.0       // 2^20

__device__ unsigned long long g_acc_pack;   // zero-initialized

__device__ __forceinline__ float warp_sum(float v) {
#pragma unroll
    for (int o = 16; o > 0; o >>= 1)
        v += __shfl_xor_sync(0xffffffff, v, o);
    return v;
}

// fast log(sigmoid(x)) = -log(1 + exp(-x)); safe for |x| << 80, rel err ~2^-21
__device__ __forceinline__ float logsig_fast(float x) {
    return -__logf(1.0f + __expf(-x));
}

__device__ __forceinline__ float dot4(float4 a, float4 b) {
    return a.x * b.x + a.y * b.y + a.z * b.z + a.w * b.w;
}

// cache policy: keep table lines resident in L2
__device__ __forceinline__ unsigned long long make_keep_policy() {
    unsigned long long pol;
    asm("createpolicy.fractional.L2::evict_last.b64 %0, 1.0;" : "=l"(pol));
    return pol;
}

// read-only vector load with L2 keep-resident policy
__device__ __forceinline__ float4 ldg_keep(const float4* p, unsigned long long pol) {
    float4 v;
    asm("ld.global.nc.L2::cache_hint.v4.f32 {%0,%1,%2,%3}, [%4], %5;"
        : "=f"(v.x), "=f"(v.y), "=f"(v.z), "=f"(v.w) : "l"(p), "l"(pol));
    return v;
}

__global__ __launch_bounds__(NTHREADS, 6)
void sg_compute_kernel(const int* __restrict__ input_idx,
                       const int* __restrict__ output_idx,
                       const int* __restrict__ neg_idx,
                       const float* __restrict__ W_in,
                       const float* __restrict__ W_out,
                       float* __restrict__ out) {
    const int warp = threadIdx.x >> 5;
    const int lane = threadIdx.x & 31;
    const int n = blockIdx.x * WARPS_PER_BLOCK + warp;

    const unsigned long long pol = make_keep_policy();

    // --- independent scalar index loads (uniform across warp, issue early) ---
    int idx[NROWS];
    idx[0] = output_idx[n];
#pragma unroll
    for (int k = 0; k < KNEG; k++)
        idx[k + 1] = neg_idx[n * KNEG + k];
    const int ii = input_idx[n];

    // --- input row: each lane holds one float4 of the 128-float row ---
    float4 a = ldg_keep(reinterpret_cast<const float4*>(W_in + (size_t)ii * DIMS) + lane, pol);

    // --- 3-deep rotated streaming of the 11 W_out rows ---
    float4 b0 = ldg_keep(reinterpret_cast<const float4*>(W_out + (size_t)idx[0] * DIMS) + lane, pol);
    float4 b1 = ldg_keep(reinterpret_cast<const float4*>(W_out + (size_t)idx[1] * DIMS) + lane, pol);
    float4 b2 = ldg_keep(reinterpret_cast<const float4*>(W_out + (size_t)idx[2] * DIMS) + lane, pol);

    float local = 0.0f;
#pragma unroll
    for (int j = 0; j < NROWS; j++) {
        float p = dot4(a, b0);
        // rotate pipeline; issue next load before the reduction chain
        b0 = b1;
        b1 = b2;
        if (j + 3 < NROWS)
            b2 = ldg_keep(reinterpret_cast<const float4*>(W_out + (size_t)idx[j + 3] * DIMS) + lane, pol);
        float d = warp_sum(p);
        // all lanes compute redundantly (same warp-issue cost, no predication)
        local += logsig_fast(j == 0 ? d : -d);
    }

    // --- block reduce ---
    __shared__ float s[WARPS_PER_BLOCK];
    if (lane == 0) s[warp] = local;
    __syncthreads();
    if (threadIdx.x == 0) {
        float t = 0.0f;
#pragma unroll
        for (int i = 0; i < WARPS_PER_BLOCK; i++) t += s[i];

        // fixed-point pack: value in [0, 2^34), counter at bit 48
        long long fixed = __double2ll_rn(((double)t + FP_BIAS) * FP_SCALE);
        unsigned long long add = (1ULL << 48) + (unsigned long long)fixed;
        unsigned long long old = atomicAdd(&g_acc_pack, add);

        if ((old >> 48) == NBLOCKS - 1) {
            // This block is last: old + add is the complete packed total.
            unsigned long long total = old + add;
            double sum = (double)(long long)(total & ((1ULL << 48) - 1)) / FP_SCALE
                         - (double)NBLOCKS * FP_BIAS;
            out[0] = (float)(sum / (double)N_SAMPLES);
            g_acc_pack = 0ULL;   // reset for next graph replay (no racers remain)
        }
    }
}

extern "C" void kernel_launch(void* const* d_in, const int* in_sizes, int n_in,
                              void* d_out, int out_size) {
    const int*   input_idx  = (const int*)d_in[0];
    const int*   output_idx = (const int*)d_in[1];
    const int*   neg_idx    = (const int*)d_in[2];
    const float* W_in       = (const float*)d_in[3];
    const float* W_out      = (const float*)d_in[4];
    float* out = (float*)d_out;

    sg_compute_kernel<<<NBLOCKS, NTHREADS>>>(
        input_idx, output_idx, neg_idx, W_in, W_out, out);
}